// round 7
// baseline (speedup 1.0000x reference)
#include <cuda_runtime.h>
#include <cuda_fp16.h>
#include <math.h>

#define TPB    1024
#define NPROD  768               // producer threads (24 warps): [256,1024)
#define NCONS  256               // consumer threads (8 warps):  [0,256)
#define CNT    8192              // points per group
#define SPG    8192              // pairs per group
#define BUF_H2 (3 * CNT)         // half2 slots per buffer (12 B/point) = 96 KB
#define SMEM_BYTES (2 * BUF_H2 * 4)   // 192 KB double buffer

__device__ double g_acc = 0.0;
__device__ unsigned int g_count = 0;

// Interleaved layout per point p:
//   buf[3p+0] = (in.x, in.y)   buf[3p+1] = (in.z, tg.z)   buf[3p+2] = (tg.x, tg.y)
__device__ __forceinline__ void stage_group(const float* __restrict__ inputs,
                                            const float* __restrict__ target,
                                            int g, __half2* __restrict__ buf,
                                            int pt)   // producer thread id 0..NPROD-1
{
    const float* in_slab = inputs + (size_t)g * CNT * 9;
    const float* tg_slab = target + (size_t)g * CNT * 9;
    #pragma unroll 4
    for (int p = pt; p < CNT; p += NPROD) {   // ~10.7 iters
        const float* ri = in_slab + (size_t)p * 9 + 3;
        const float* rt = tg_slab + (size_t)p * 9 + 3;
        float ix = __ldg(ri + 0), iy = __ldg(ri + 1), iz = __ldg(ri + 2);
        float tx = __ldg(rt + 0), ty = __ldg(rt + 1), tz = __ldg(rt + 2);
        buf[3 * p + 0] = __floats2half2_rn(ix, iy);
        buf[3 * p + 1] = __floats2half2_rn(iz, tz);
        buf[3 * p + 2] = __floats2half2_rn(tx, ty);
    }
}

__device__ __forceinline__ float pair_term(int l, int r, const __half2* __restrict__ buf)
{
    float2 a  = __half22float2(buf[3 * l + 0]);
    float2 mz = __half22float2(buf[3 * l + 1]);
    float2 c  = __half22float2(buf[3 * l + 2]);
    float2 b  = __half22float2(buf[3 * r + 0]);
    float2 nz = __half22float2(buf[3 * r + 1]);
    float2 d  = __half22float2(buf[3 * r + 2]);

    float ux = a.x - b.x, uy = a.y - b.y, uz = mz.x - nz.x;
    float d_in = sqrtf(fmaf(ux, ux, fmaf(uy, uy, uz * uz)));

    float vx = c.x - d.x, vy = c.y - d.y, vz = mz.y - nz.y;
    float d_tg = sqrtf(fmaf(vx, vx, fmaf(vy, vy, vz * vz)));

    float t = d_in - d_tg;
    return t * t;
}

__device__ __forceinline__ float consume_group(const int* __restrict__ left,
                                               const int* __restrict__ right,
                                               int g, const __half2* __restrict__ buf,
                                               int ct)  // consumer thread id 0..NCONS-1
{
    const int4* Lg = (const int4*)(left  + (size_t)g * SPG);
    const int4* Rg = (const int4*)(right + (size_t)g * SPG);
    float acc = 0.0f;
    #pragma unroll
    for (int j = 0; j < SPG / (4 * NCONS); j++) {   // 8 iters, 4 pairs each
        const int i = ct + j * NCONS;
        int4 L = __ldg(Lg + i);
        int4 R = __ldg(Rg + i);
        acc += pair_term(L.x & (CNT - 1), R.x & (CNT - 1), buf);
        acc += pair_term(L.y & (CNT - 1), R.y & (CNT - 1), buf);
        acc += pair_term(L.z & (CNT - 1), R.z & (CNT - 1), buf);
        acc += pair_term(L.w & (CNT - 1), R.w & (CNT - 1), buf);
    }
    return acc;
}

__global__ void __launch_bounds__(TPB, 1)
rgn_ws_kernel(const float* __restrict__ inputs,
              const float* __restrict__ target,
              const int* __restrict__ left,
              const int* __restrict__ right,
              float* __restrict__ out,
              int npairs, int ngroups)
{
    extern __shared__ unsigned char smem_raw[];
    __half2* buf0 = (__half2*)smem_raw;
    __half2* buf1 = buf0 + BUF_H2;

    const bool is_prod = (threadIdx.x >= NCONS);
    const int  role_t  = is_prod ? (threadIdx.x - NCONS) : threadIdx.x;

    // groups for this CTA: blockIdx.x + r*gridDim.x, r = 0..K-1
    const int K = (ngroups - blockIdx.x + gridDim.x - 1) / gridDim.x;

    float acc = 0.0f;
    for (int r = 0; r <= K; r++) {
        __syncthreads();
        if (is_prod) {
            if (r < K) {
                __half2* b = (r & 1) ? buf1 : buf0;
                stage_group(inputs, target, blockIdx.x + r * gridDim.x, b, role_t);
            }
        } else {
            if (r >= 1) {
                const __half2* b = ((r - 1) & 1) ? buf1 : buf0;
                acc += consume_group(left, right, blockIdx.x + (r - 1) * gridDim.x, b, role_t);
            }
        }
    }
    __syncthreads();

    // block reduce (producers carry 0)
    #pragma unroll
    for (int off = 16; off > 0; off >>= 1)
        acc += __shfl_down_sync(0xFFFFFFFFu, acc, off);

    __shared__ float warp_sums[TPB / 32];
    const int lane = threadIdx.x & 31;
    const int wid  = threadIdx.x >> 5;
    if (lane == 0) warp_sums[wid] = acc;
    __syncthreads();

    if (wid == 0) {
        float s = (lane < TPB / 32) ? warp_sums[lane] : 0.0f;
        #pragma unroll
        for (int off = (TPB / 64); off > 0; off >>= 1)
            s += __shfl_down_sync(0xFFFFFFFFu, s, off);

        if (lane == 0) {
            atomicAdd(&g_acc, (double)s);
            __threadfence();
            unsigned int done = atomicAdd(&g_count, 1u);
            if (done == gridDim.x - 1) {
                out[0] = (float)(g_acc / (double)npairs);
                g_acc = 0.0;     // reset for next graph replay
                g_count = 0;
            }
        }
    }
}

extern "C" void kernel_launch(void* const* d_in, const int* in_sizes, int n_in,
                              void* d_out, int out_size) {
    const float* inputs = (const float*)d_in[0];
    const float* target = (const float*)d_in[1];
    const int*   left   = (const int*)d_in[2];
    const int*   right  = (const int*)d_in[3];
    float* out = (float*)d_out;

    int npairs  = in_sizes[2];
    int ngroups = npairs / SPG;   // 512

    static int num_sms = 0;
    if (num_sms == 0) {
        cudaDeviceProp prop;
        cudaGetDeviceProperties(&prop, 0);
        num_sms = prop.multiProcessorCount;   // 152 on GB300
    }

    // Prefer a grid that divides ngroups exactly (zero ragged tail).
    int grid;
    if (num_sms >= 128 && (ngroups % 128) == 0) grid = 128;
    else grid = (num_sms < ngroups) ? num_sms : ngroups;

    cudaFuncSetAttribute(rgn_ws_kernel,
                         cudaFuncAttributeMaxDynamicSharedMemorySize, SMEM_BYTES);

    rgn_ws_kernel<<<grid, TPB, SMEM_BYTES>>>(inputs, target, left, right,
                                             out, npairs, ngroups);
}

// round 8
// speedup vs baseline: 1.0548x; 1.0548x over previous
#include <cuda_runtime.h>
#include <cuda_fp16.h>
#include <stdint.h>

#define TPB        1024
#define CNT        8192
#define SPG        8192
#define CHUNK_PTS  512
#define NCHUNK     (CNT / CHUNK_PTS)            // 16 chunks per group
#define F4_PER_ARR (CHUNK_PTS * 9 / 4)          // 1152 float4 per array per chunk
#define CHUNK_F4   (2 * F4_PER_ARR)             // 2304
#define RAW_SLOT_B (CHUNK_PTS * 9 * 4 * 2)      // 36864 B per slot (both arrays)
#define NSLOT      3
#define BUF_B      (12 * CNT)                   // 98304 B final fp16 buffer
#define SMEM_BYTES (BUF_B + NSLOT * RAW_SLOT_B) // 208896 B

__device__ double g_acc = 0.0;
__device__ unsigned int g_count = 0;

__device__ __forceinline__ uint32_t smem_u32(const void* p) {
    return (uint32_t)__cvta_generic_to_shared(p);
}
__device__ __forceinline__ void cp_async16(uint32_t dst, const void* src) {
    asm volatile("cp.async.cg.shared.global [%0], [%1], 16;" :: "r"(dst), "l"(src));
}
#define CP_COMMIT() asm volatile("cp.async.commit_group;")
#define CP_WAIT2()  asm volatile("cp.async.wait_group 2;" ::: "memory")

__device__ __forceinline__ float pair_term(int l, int r, const __half2* __restrict__ buf)
{
    float2 a  = __half22float2(buf[3 * l + 0]);   // in.xy
    float2 mz = __half22float2(buf[3 * l + 1]);   // (in.z, tg.z)
    float2 c  = __half22float2(buf[3 * l + 2]);   // tg.xy
    float2 b  = __half22float2(buf[3 * r + 0]);
    float2 nz = __half22float2(buf[3 * r + 1]);
    float2 d  = __half22float2(buf[3 * r + 2]);

    float ux = a.x - b.x, uy = a.y - b.y, uz = mz.x - nz.x;
    float d_in = sqrtf(fmaf(ux, ux, fmaf(uy, uy, uz * uz)));

    float vx = c.x - d.x, vy = c.y - d.y, vz = mz.y - nz.y;
    float d_tg = sqrtf(fmaf(vx, vx, fmaf(vy, vy, vz * vz)));

    float t = d_in - d_tg;
    return t * t;
}

struct IssueCtx {
    const float* inputs;
    const float* target;
    uint32_t raw_u32;
    int grid;
    int bx;
};

__device__ __forceinline__ void issue_chunk(const IssueCtx& cx, int cc)
{
    const int g  = cx.bx + (cc >> 4) * cx.grid;
    const int ci = cc & (NCHUNK - 1);
    const float4* sin = (const float4*)(cx.inputs + (size_t)g * CNT * 9 + (size_t)ci * CHUNK_PTS * 9);
    const float4* stg = (const float4*)(cx.target + (size_t)g * CNT * 9 + (size_t)ci * CHUNK_PTS * 9);
    const uint32_t slot = cx.raw_u32 + (uint32_t)(cc % NSLOT) * RAW_SLOT_B;
    #pragma unroll 3
    for (int i = threadIdx.x; i < CHUNK_F4; i += TPB) {
        const float4* s = (i < F4_PER_ARR) ? (sin + i) : (stg + (i - F4_PER_ARR));
        cp_async16(slot + (uint32_t)i * 16u, s);
    }
}

__global__ void __launch_bounds__(TPB, 1)
rgn_stream_kernel(const float* __restrict__ inputs,
                  const float* __restrict__ target,
                  const int* __restrict__ left,
                  const int* __restrict__ right,
                  float* __restrict__ out,
                  int npairs, int ngroups)
{
    extern __shared__ unsigned char smem[];
    unsigned char* bufb = smem;                        // fp16 buffer, 12 B/point
    __half2* buf = (__half2*)smem;
    float* raw = (float*)(smem + BUF_B);               // chunk ring, NSLOT slots
    const uint32_t raw_u32 = smem_u32(raw);

    IssueCtx cx{inputs, target, raw_u32, (int)gridDim.x, (int)blockIdx.x};

    const int K = (ngroups - blockIdx.x + gridDim.x - 1) / gridDim.x;
    const int total = K * NCHUNK;

    if (0 < total) issue_chunk(cx, 0);
    CP_COMMIT();
    if (1 < total) issue_chunk(cx, 1);
    CP_COMMIT();

    float acc = 0.0f;
    for (int cc = 0; cc < total; cc++) {
        if (cc + 2 < total) issue_chunk(cx, cc + 2);
        CP_COMMIT();
        CP_WAIT2();                 // chunk cc complete (2 newest groups may be pending)
        __syncthreads();

        // demux chunk cc: raw slot -> fp16 buffer (stride-9 LDS = bank-conflict-free)
        {
            const float* slot = raw + (size_t)(cc % NSLOT) * (RAW_SLOT_B / 4);
            const int ci = cc & (NCHUNK - 1);
            const int t = threadIdx.x;
            if (t < CHUNK_PTS) {
                const int q = t;
                const float* r = slot + 9 * q + 3;                 // inputs CA row
                float x = r[0], y = r[1], z = r[2];
                const int p = ci * CHUNK_PTS + q;
                *(__half2*)(bufb + 12 * p)     = __floats2half2_rn(x, y);
                *(__half*) (bufb + 12 * p + 4) = __float2half_rn(z);
            } else {
                const int q = t - CHUNK_PTS;
                const float* r = slot + CHUNK_PTS * 9 + 9 * q + 3; // target CA row
                float x = r[0], y = r[1], z = r[2];
                const int p = ci * CHUNK_PTS + q;
                *(__half*) (bufb + 12 * p + 6) = __float2half_rn(z);
                *(__half2*)(bufb + 12 * p + 8) = __floats2half2_rn(x, y);
            }
        }
        __syncthreads();

        if ((cc & (NCHUNK - 1)) == (NCHUNK - 1)) {
            // group fully staged; consume (next group's first 2 chunks already in flight)
            const int g = blockIdx.x + (cc >> 4) * gridDim.x;
            const int4* Lg = (const int4*)(left  + (size_t)g * SPG);
            const int4* Rg = (const int4*)(right + (size_t)g * SPG);
            #pragma unroll
            for (int j = 0; j < SPG / (4 * TPB); j++) {   // 2 iters, 4 pairs each
                const int i = threadIdx.x + j * TPB;
                int4 L = __ldg(Lg + i);
                int4 R = __ldg(Rg + i);
                acc += pair_term(L.x & (CNT - 1), R.x & (CNT - 1), buf);
                acc += pair_term(L.y & (CNT - 1), R.y & (CNT - 1), buf);
                acc += pair_term(L.z & (CNT - 1), R.z & (CNT - 1), buf);
                acc += pair_term(L.w & (CNT - 1), R.w & (CNT - 1), buf);
            }
            __syncthreads();   // buf reads done before next group's demux overwrites
        }
    }

    // block reduce
    #pragma unroll
    for (int off = 16; off > 0; off >>= 1)
        acc += __shfl_down_sync(0xFFFFFFFFu, acc, off);

    __shared__ float warp_sums[TPB / 32];
    const int lane = threadIdx.x & 31;
    const int wid  = threadIdx.x >> 5;
    if (lane == 0) warp_sums[wid] = acc;
    __syncthreads();

    if (wid == 0) {
        float s = (lane < TPB / 32) ? warp_sums[lane] : 0.0f;
        #pragma unroll
        for (int off = 16; off > 0; off >>= 1)
            s += __shfl_down_sync(0xFFFFFFFFu, s, off);

        if (lane == 0) {
            atomicAdd(&g_acc, (double)s);
            __threadfence();
            unsigned int done = atomicAdd(&g_count, 1u);
            if (done == gridDim.x - 1) {
                out[0] = (float)(g_acc / (double)npairs);
                g_acc = 0.0;     // reset for next graph replay
                g_count = 0;
            }
        }
    }
}

extern "C" void kernel_launch(void* const* d_in, const int* in_sizes, int n_in,
                              void* d_out, int out_size) {
    const float* inputs = (const float*)d_in[0];
    const float* target = (const float*)d_in[1];
    const int*   left   = (const int*)d_in[2];
    const int*   right  = (const int*)d_in[3];
    float* out = (float*)d_out;

    int npairs  = in_sizes[2];
    int ngroups = npairs / SPG;   // 512

    static int num_sms = 0;
    if (num_sms == 0) {
        cudaDeviceProp prop;
        cudaGetDeviceProperties(&prop, 0);
        num_sms = prop.multiProcessorCount;   // 152 on GB300
    }
    int grid = (num_sms < ngroups) ? num_sms : ngroups;

    cudaFuncSetAttribute(rgn_stream_kernel,
                         cudaFuncAttributeMaxDynamicSharedMemorySize, SMEM_BYTES);

    rgn_stream_kernel<<<grid, TPB, SMEM_BYTES>>>(inputs, target, left, right,
                                                 out, npairs, ngroups);
}

// round 9
// speedup vs baseline: 1.1429x; 1.0835x over previous
#include <cuda_runtime.h>
#include <cuda_fp16.h>
#include <stdint.h>

#define TPB        1024
#define CNT        8192
#define SPG        8192
#define CHUNK_PTS  512
#define NCHUNK     (CNT / CHUNK_PTS)            // 16 chunks per group
#define ARR_BYTES  (CHUNK_PTS * 9 * 4)          // 18432 B per array per chunk
#define RAW_SLOT_B (2 * ARR_BYTES)              // 36864 B per slot
#define NSLOT      3
#define BUF_B      (12 * CNT)                   // 98304 B fp16 point buffer
#define MBAR_OFF   (BUF_B + NSLOT * RAW_SLOT_B)
#define SMEM_BYTES (MBAR_OFF + 64)              // 208960 B

__device__ double g_acc = 0.0;
__device__ unsigned int g_count = 0;

__device__ __forceinline__ uint32_t smem_u32(const void* p) {
    return (uint32_t)__cvta_generic_to_shared(p);
}

__device__ __forceinline__ void mbar_init(uint32_t mbar, uint32_t cnt) {
    asm volatile("mbarrier.init.shared.b64 [%0], %1;" :: "r"(mbar), "r"(cnt) : "memory");
}
__device__ __forceinline__ void mbar_expect_tx(uint32_t mbar, uint32_t bytes) {
    asm volatile("mbarrier.arrive.expect_tx.shared.b64 _, [%0], %1;"
                 :: "r"(mbar), "r"(bytes) : "memory");
}
__device__ __forceinline__ void mbar_wait(uint32_t mbar, uint32_t parity) {
    uint32_t done;
    asm volatile(
        "{\n\t.reg .pred p;\n\t"
        "mbarrier.try_wait.parity.acquire.cta.shared::cta.b64 p, [%1], %2;\n\t"
        "selp.b32 %0, 1, 0, p;\n\t}"
        : "=r"(done) : "r"(mbar), "r"(parity) : "memory");
    if (!done) {
        asm volatile(
            "{\n\t.reg .pred P1;\n\t"
            "W_%=:\n\t"
            "mbarrier.try_wait.parity.acquire.cta.shared::cta.b64 P1, [%0], %1, 0x989680;\n\t"
            "@P1 bra.uni D_%=;\n\t"
            "bra.uni W_%=;\n\t"
            "D_%=:\n\t}"
            :: "r"(mbar), "r"(parity) : "memory");
    }
}
__device__ __forceinline__ void bulk_copy(uint32_t dst, const void* src,
                                          uint32_t bytes, uint32_t mbar) {
    asm volatile(
        "cp.async.bulk.shared::cta.global.mbarrier::complete_tx::bytes [%0], [%1], %2, [%3];"
        :: "r"(dst), "l"(src), "r"(bytes), "r"(mbar) : "memory");
}

__device__ __forceinline__ float pair_term(int l, int r, const __half2* __restrict__ buf)
{
    float2 a  = __half22float2(buf[3 * l + 0]);   // in.xy
    float2 mz = __half22float2(buf[3 * l + 1]);   // (in.z, tg.z)
    float2 c  = __half22float2(buf[3 * l + 2]);   // tg.xy
    float2 b  = __half22float2(buf[3 * r + 0]);
    float2 nz = __half22float2(buf[3 * r + 1]);
    float2 d  = __half22float2(buf[3 * r + 2]);

    float ux = a.x - b.x, uy = a.y - b.y, uz = mz.x - nz.x;
    float d_in = sqrtf(fmaf(ux, ux, fmaf(uy, uy, uz * uz)));

    float vx = c.x - d.x, vy = c.y - d.y, vz = mz.y - nz.y;
    float d_tg = sqrtf(fmaf(vx, vx, fmaf(vy, vy, vz * vz)));

    float t = d_in - d_tg;
    return t * t;
}

__global__ void __launch_bounds__(TPB, 1)
rgn_bulk_kernel(const float* __restrict__ inputs,
                const float* __restrict__ target,
                const int* __restrict__ left,
                const int* __restrict__ right,
                float* __restrict__ out,
                int npairs, int ngroups)
{
    extern __shared__ unsigned char smem[];
    unsigned char* bufb = smem;                  // fp16 buffer, 12 B/point
    __half2* buf = (__half2*)smem;
    float* raw = (float*)(smem + BUF_B);         // NSLOT raw chunk slots
    const uint32_t raw_u32 = smem_u32(raw);
    const uint32_t mb0 = smem_u32(smem + MBAR_OFF);

    const int K = (ngroups - blockIdx.x + gridDim.x - 1) / gridDim.x;
    const int total = K * NCHUNK;

    if (threadIdx.x == 0) {
        #pragma unroll
        for (int s = 0; s < NSLOT; s++) mbar_init(mb0 + 8 * s, 1);
    }
    __syncthreads();

    // issue a chunk: 2 bulk copies + expect_tx, single thread
    auto issue = [&](int cc) {
        const int g  = blockIdx.x + (cc >> 4) * gridDim.x;
        const int ci = cc & (NCHUNK - 1);
        const uint32_t slot = raw_u32 + (uint32_t)(cc % NSLOT) * RAW_SLOT_B;
        const uint32_t mbar = mb0 + 8 * (cc % NSLOT);
        const float* sin = inputs + (size_t)g * CNT * 9 + (size_t)ci * CHUNK_PTS * 9;
        const float* stg = target + (size_t)g * CNT * 9 + (size_t)ci * CHUNK_PTS * 9;
        mbar_expect_tx(mbar, RAW_SLOT_B);
        bulk_copy(slot, sin, ARR_BYTES, mbar);
        bulk_copy(slot + ARR_BYTES, stg, ARR_BYTES, mbar);
    };

    if (threadIdx.x == 0) {
        if (0 < total) issue(0);
        if (1 < total) issue(1);
    }

    float acc = 0.0f;
    for (int cc = 0; cc < total; cc++) {
        if (threadIdx.x == 0 && cc + 2 < total) issue(cc + 2);

        mbar_wait(mb0 + 8 * (cc % NSLOT), (uint32_t)((cc / NSLOT) & 1));

        // demux chunk cc: raw slot -> fp16 buffer (stride-9 word LDS: conflict-free)
        {
            const float* slot = raw + (size_t)(cc % NSLOT) * (RAW_SLOT_B / 4);
            const int ci = cc & (NCHUNK - 1);
            const int t = threadIdx.x;
            if (t < CHUNK_PTS) {
                const float* r = slot + 9 * t + 3;                  // inputs CA row
                const int p = ci * CHUNK_PTS + t;
                *(__half2*)(bufb + 12 * p)     = __floats2half2_rn(r[0], r[1]);
                *(__half*) (bufb + 12 * p + 4) = __float2half_rn(r[2]);
            } else {
                const int q = t - CHUNK_PTS;
                const float* r = slot + CHUNK_PTS * 9 + 9 * q + 3;  // target CA row
                const int p = ci * CHUNK_PTS + q;
                *(__half*) (bufb + 12 * p + 6) = __float2half_rn(r[2]);
                *(__half2*)(bufb + 12 * p + 8) = __floats2half2_rn(r[0], r[1]);
            }
        }
        __syncthreads();   // demux reads of this slot done -> safe to reissue; buf writes visible

        if ((cc & (NCHUNK - 1)) == (NCHUNK - 1)) {
            // group fully staged; consume it (next group's chunks already in flight)
            const int g = blockIdx.x + (cc >> 4) * gridDim.x;
            const int4* Lg = (const int4*)(left  + (size_t)g * SPG);
            const int4* Rg = (const int4*)(right + (size_t)g * SPG);
            #pragma unroll
            for (int j = 0; j < SPG / (4 * TPB); j++) {   // 2 iters, 4 pairs each
                const int i = threadIdx.x + j * TPB;
                int4 L = __ldg(Lg + i);
                int4 R = __ldg(Rg + i);
                acc += pair_term(L.x & (CNT - 1), R.x & (CNT - 1), buf);
                acc += pair_term(L.y & (CNT - 1), R.y & (CNT - 1), buf);
                acc += pair_term(L.z & (CNT - 1), R.z & (CNT - 1), buf);
                acc += pair_term(L.w & (CNT - 1), R.w & (CNT - 1), buf);
            }
            __syncthreads();   // buf reads done before next group's demux overwrites
        }
    }

    // block reduce
    #pragma unroll
    for (int off = 16; off > 0; off >>= 1)
        acc += __shfl_down_sync(0xFFFFFFFFu, acc, off);

    __shared__ float warp_sums[TPB / 32];
    const int lane = threadIdx.x & 31;
    const int wid  = threadIdx.x >> 5;
    if (lane == 0) warp_sums[wid] = acc;
    __syncthreads();

    if (wid == 0) {
        float s = (lane < TPB / 32) ? warp_sums[lane] : 0.0f;
        #pragma unroll
        for (int off = 16; off > 0; off >>= 1)
            s += __shfl_down_sync(0xFFFFFFFFu, s, off);

        if (lane == 0) {
            atomicAdd(&g_acc, (double)s);
            __threadfence();
            unsigned int done = atomicAdd(&g_count, 1u);
            if (done == gridDim.x - 1) {
                out[0] = (float)(g_acc / (double)npairs);
                g_acc = 0.0;     // reset for next graph replay
                g_count = 0;
            }
        }
    }
}

extern "C" void kernel_launch(void* const* d_in, const int* in_sizes, int n_in,
                              void* d_out, int out_size) {
    const float* inputs = (const float*)d_in[0];
    const float* target = (const float*)d_in[1];
    const int*   left   = (const int*)d_in[2];
    const int*   right  = (const int*)d_in[3];
    float* out = (float*)d_out;

    int npairs  = in_sizes[2];
    int ngroups = npairs / SPG;   // 512

    static int num_sms = 0;
    if (num_sms == 0) {
        cudaDeviceProp prop;
        cudaGetDeviceProperties(&prop, 0);
        num_sms = prop.multiProcessorCount;   // 152 on GB300
    }
    int grid = (num_sms < ngroups) ? num_sms : ngroups;

    cudaFuncSetAttribute(rgn_bulk_kernel,
                         cudaFuncAttributeMaxDynamicSharedMemorySize, SMEM_BYTES);

    rgn_bulk_kernel<<<grid, TPB, SMEM_BYTES>>>(inputs, target, left, right,
                                               out, npairs, ngroups);
}